// round 17
// baseline (speedup 1.0000x reference)
#include <cuda_runtime.h>
#include <cuda_fp16.h>
#include <cstdint>

// ============================================================================
// Problem constants
// ============================================================================
#define MDIM   65536      // B*N = 2048*32
#define KDIM   1024       // model dim
#define NQKV   3072       // 3*DIM
#define NPROJ  1024
#define HEADS  16
#define HEAD_D 64
#define SEQ    32
#define BATCH  2048
#define KT     32         // k-tiles of 32 per K=1024

// fp16 tiled layout: tile = 128 rows x 32 k-halfs = 64 B/row, pitch 64, 8 KB
static constexpr int TILE16 = 8192;

// ============================================================================
// Scratch (allocation-free rule: __device__ globals)
// ============================================================================
__device__ __align__(256) __half g_qkv16[(size_t)MDIM * NQKV];           // 402 MB fp16
__device__ __align__(256) unsigned char g_xs16 [(size_t)(MDIM/128) * KT * TILE16]; // 134 MB
__device__ __align__(256) unsigned char g_at16 [(size_t)(MDIM/128) * KT * TILE16]; // 134 MB
__device__ __align__(256) unsigned char g_wq16 [(size_t)(NQKV/128) * KT * TILE16]; //   6 MB
__device__ __align__(256) unsigned char g_wp16 [(size_t)(NPROJ/128) * KT * TILE16];//   2 MB

// ============================================================================
// Helpers — BASELINE PTX ONLY (compute_103 target)
// ============================================================================

// m16n8k16 fp16 HMMA, fp32 accumulate
__device__ __forceinline__ void mma_f16(float& c0, float& c1, float& c2, float& c3,
                                        uint32_t a0, uint32_t a1, uint32_t a2, uint32_t a3,
                                        uint32_t b0, uint32_t b1) {
    asm volatile(
        "mma.sync.aligned.m16n8k16.row.col.f32.f16.f16.f32 "
        "{%0,%1,%2,%3}, {%4,%5,%6,%7}, {%8,%9}, {%0,%1,%2,%3};"
        : "+f"(c0), "+f"(c1), "+f"(c2), "+f"(c3)
        : "r"(a0), "r"(a1), "r"(a2), "r"(a3), "r"(b0), "r"(b1));
}

// ----------------------------------------------------------------------------
// fp16 tiled layout (single source of truth) — see R14/R15.
// One LDS.128 at (row, lc) yields the fragments for BOTH k16 steps;
// quarter-warp phases hit 8 distinct 16B slots -> conflict-free, pitch 64.
// ----------------------------------------------------------------------------
__device__ __forceinline__ size_t tiled16_byte(int row, int col) {
    int kt = col >> 5, c = col & 31;
    int ks = (c >> 4) & 1;
    int j  = c & 15;
    int lc = (j & 7) >> 1;
    int p  = ((j >> 3) << 1) | (c & 1);
    size_t tile = ((size_t)(row >> 7) * KT + kt) * (size_t)TILE16;
    return tile + (size_t)((row & 127) << 6) + lc * 16 + ks * 8 + p * 2;
}

// ============================================================================
// Pre-pass: fp32 row-major -> fp16 (RN) tiled scratch
// ============================================================================
__global__ void __launch_bounds__(256)
convert_tile16_kernel(const float* __restrict__ src, unsigned char* __restrict__ dst,
                      int R, int K)
{
    size_t gid = (size_t)blockIdx.x * 256 + threadIdx.x;
    size_t total = ((size_t)R * K) >> 2;
    if (gid >= total) return;
    int kq  = K >> 2;
    int row = (int)(gid / kq);
    int c4  = (int)(gid % kq) << 2;
    float4 v = *(const float4*)(src + (size_t)row * K + c4);
    __half2 h0 = __floats2half2_rn(v.x, v.y);
    __half2 h1 = __floats2half2_rn(v.z, v.w);
    *(__half2*)(dst + tiled16_byte(row, c4))     = h0;
    *(__half2*)(dst + tiled16_byte(row, c4 + 2)) = h1;
}

// ============================================================================
// GEMM: C[M,N] = At[M,K] @ Bt[N,K]^T + bias   (inputs pre-tiled fp16)
//   CTA 128x128, 8 warps (2x4) of 64x32 tiles, 6-stage cp.async, sync per
//   kt-pair. R17: the kt-PAIR is one fused software-pipelined stream —
//   A0(k1) prefetches into the free av buffer during k0's mt=3 MMAs and
//   B(k1) reloads bv right after k0's last MMA issue, so k1's 6 cold LDS
//   all hide under k0's MMA shadow. Only the post-barrier burst remains.
//   Register-neutral (bv reused, av alternation crosses the kt boundary).
// ============================================================================
static constexpr int STAGES = 6;
static constexpr int STAGE_BYTES = 2 * TILE16;          // A 8K + B 8K
static constexpr int GEMM_SMEM = STAGES * STAGE_BYTES;  // 96 KB -> 2 CTAs/SM

template<bool HALF_OUT>
__global__ void __launch_bounds__(256, 2)
gemm_f16_kernel(const unsigned char* __restrict__ At, const unsigned char* __restrict__ Bt,
                const float* __restrict__ bias, void* __restrict__ Cv,
                int M, int N)
{
    extern __shared__ char smem[];
    uint32_t sb;
    asm("{ .reg .u64 t; cvta.to.shared.u64 t, %1; cvt.u32.u64 %0, t; }"
        : "=r"(sb) : "l"(smem));

    const int tid  = threadIdx.x;
    const int lane = tid & 31;
    const int w    = tid >> 5;
    const int wm   = w >> 2;     // 0..1  (64-row half)
    const int wn   = w & 3;      // 0..3  (32-col band)
    const int lg   = lane >> 2;  // 0..7
    const int lc   = lane & 3;   // 0..3

    // ---- grid swizzle: groups of 16 M-tiles, N-tile outer within group ----
    const int tiles_n = N >> 7;
    const int per = 16 * tiles_n;
    const int grp = blockIdx.x / per;
    const int r_  = blockIdx.x % per;
    const int mtile = grp * 16 + (r_ % 16);
    const int ntile = r_ / 16;
    const int m0 = mtile << 7, n0 = ntile << 7;

    // ---- producer ----
    const unsigned char* Abase = At + (size_t)mtile * KT * TILE16;
    const unsigned char* Bbase = Bt + (size_t)ntile * KT * TILE16;
    const int o0 = tid * 16;
    const int o1 = (tid + 256) * 16;

    auto issue = [&](int kt) {
        const int s = kt % STAGES;
        const unsigned char* asrc = Abase + (size_t)kt * TILE16;
        const unsigned char* bsrc = Bbase + (size_t)kt * TILE16;
        uint32_t ad = sb + s * STAGE_BYTES;
        uint32_t bd = ad + TILE16;
        asm volatile("cp.async.cg.shared.global [%0], [%1], 16;"
                     :: "r"(ad + o0), "l"(asrc + o0));
        asm volatile("cp.async.cg.shared.global [%0], [%1], 16;"
                     :: "r"(bd + o0), "l"(bsrc + o0));
        asm volatile("cp.async.cg.shared.global [%0], [%1], 16;"
                     :: "r"(ad + o1), "l"(asrc + o1));
        asm volatile("cp.async.cg.shared.global [%0], [%1], 16;"
                     :: "r"(bd + o1), "l"(bsrc + o1));
        asm volatile("cp.async.commit_group;" ::: "memory");
    };

    // ---- consumer addresses ----
    uint32_t baseA[4], baseB[4];
#pragma unroll
    for (int mt = 0; mt < 4; ++mt)
        baseA[mt] = (uint32_t)((wm * 64 + mt * 16 + lg) << 6) + (uint32_t)(lc * 16);
#pragma unroll
    for (int nt = 0; nt < 4; ++nt)
        baseB[nt] = (uint32_t)TILE16 + (uint32_t)((wn * 32 + nt * 8 + lg) << 6)
                  + (uint32_t)(lc * 16);

    float acc[4][4][4];
#pragma unroll
    for (int mt = 0; mt < 4; ++mt)
#pragma unroll
        for (int nt = 0; nt < 4; ++nt)
#pragma unroll
            for (int i = 0; i < 4; ++i) acc[mt][nt][i] = 0.f;

    // fragment registers: bv single-buffered (reloaded mid-pair under MMA
    // shadow), av double-buffered across mt AND across the kt boundary
    uint32_t bv[4][4];
    uint32_t av[2][2][4];

    auto ldB = [&](uint32_t sg) {
#pragma unroll
        for (int nt = 0; nt < 4; ++nt) {
            uint32_t bd = sg + baseB[nt];
            asm("ld.shared.v4.b32 {%0,%1,%2,%3}, [%4];"
                : "=r"(bv[nt][0]), "=r"(bv[nt][1]),
                  "=r"(bv[nt][2]), "=r"(bv[nt][3]) : "r"(bd));
        }
    };
    auto ldA = [&](int buf, int mt, uint32_t sg) {
        uint32_t ad = sg + baseA[mt];
        asm("ld.shared.v4.b32 {%0,%1,%2,%3}, [%4];"
            : "=r"(av[buf][0][0]), "=r"(av[buf][0][1]),
              "=r"(av[buf][0][2]), "=r"(av[buf][0][3]) : "r"(ad));
        asm("ld.shared.v4.b32 {%0,%1,%2,%3}, [%4+512];"
            : "=r"(av[buf][1][0]), "=r"(av[buf][1][1]),
              "=r"(av[buf][1][2]), "=r"(av[buf][1][3]) : "r"(ad));
    };
    auto mmas = [&](int mt, int buf) {
#pragma unroll
        for (int nt = 0; nt < 4; ++nt) {
            mma_f16(acc[mt][nt][0], acc[mt][nt][1], acc[mt][nt][2], acc[mt][nt][3],
                    av[buf][0][0], av[buf][1][0], av[buf][0][1], av[buf][1][1],
                    bv[nt][0], bv[nt][1]);
            mma_f16(acc[mt][nt][0], acc[mt][nt][1], acc[mt][nt][2], acc[mt][nt][3],
                    av[buf][0][2], av[buf][1][2], av[buf][0][3], av[buf][1][3],
                    bv[nt][2], bv[nt][3]);
        }
    };

    issue(0); issue(1); issue(2); issue(3);

#pragma unroll 1
    for (int p = 0; p < KT / 2; ++p) {
        const int k0 = 2 * p;
        asm volatile("cp.async.wait_group 2;" ::: "memory");
        __syncthreads();
        if (k0 + 4 < KT) issue(k0 + 4);
        if (k0 + 5 < KT) issue(k0 + 5);

        const uint32_t sg0 = sb + (uint32_t)((k0 % STAGES) * STAGE_BYTES);
        const uint32_t sg1 = sb + (uint32_t)(((k0 + 1) % STAGES) * STAGE_BYTES);

        // ---- fused kt-pair pipeline ----
        ldB(sg0); ldA(0, 0, sg0);          // post-barrier cold burst (6 LDS)
        ldA(1, 1, sg0); mmas(0, 0);
        ldA(0, 2, sg0); mmas(1, 1);
        ldA(1, 3, sg0); mmas(2, 0);
        ldA(0, 0, sg1); mmas(3, 1);        // A0(k1) under k0 mt=3 MMAs
        ldB(sg1);                          // B(k1) under k0 MMA shadow (WAR ok)
        ldA(1, 1, sg1); mmas(0, 0);
        ldA(0, 2, sg1); mmas(1, 1);
        ldA(1, 3, sg1); mmas(2, 0);
        mmas(3, 1);
    }

    // ---- epilogue ----
#pragma unroll
    for (int nt = 0; nt < 4; ++nt) {
        const int col = n0 + wn * 32 + nt * 8 + 2 * lc;
        const float b0 = __ldg(bias + col), b1 = __ldg(bias + col + 1);
#pragma unroll
        for (int mt = 0; mt < 4; ++mt) {
            const int row = m0 + wm * 64 + mt * 16 + lg;
            if (HALF_OUT) {
                __half* C16 = (__half*)Cv;
                *(__half2*)(C16 + (size_t)row * N + col) =
                    __floats2half2_rn(acc[mt][nt][0] + b0, acc[mt][nt][1] + b1);
                *(__half2*)(C16 + (size_t)(row + 8) * N + col) =
                    __floats2half2_rn(acc[mt][nt][2] + b0, acc[mt][nt][3] + b1);
            } else {
                float* C = (float*)Cv;
                *(float2*)(C + (size_t)row * N + col) =
                    make_float2(acc[mt][nt][0] + b0, acc[mt][nt][1] + b1);
                *(float2*)(C + (size_t)(row + 8) * N + col) =
                    make_float2(acc[mt][nt][2] + b0, acc[mt][nt][3] + b1);
            }
        }
    }
}

// ============================================================================
// Attention: per (b,h): s = q k^T * 0.125 + rel_bias[h]; p = softmax; o = p v
// qkv read fp16 (halved traffic), math fp32, output fp16-tiled.
// ============================================================================
__global__ void __launch_bounds__(128)
attn_kernel(const __half* __restrict__ qkv, const float* __restrict__ rel_bias,
            unsigned char* __restrict__ attn_ts)
{
    __shared__ float q[32][65], k[32][65], v[32][65], s[32][33];
    const int bh = blockIdx.x;
    const int b = bh >> 4, h = bh & 15;
    const int tid = threadIdx.x;

    const size_t base = (size_t)b * SEQ * NQKV + (size_t)h * HEAD_D;
    for (int i = tid; i < SEQ * HEAD_D / 2; i += 128) {
        int n = i >> 5, d2 = (i & 31) << 1;
        size_t a = base + (size_t)n * NQKV + d2;
        float2 fq = __half22float2(*(const __half2*)(qkv + a));
        float2 fk = __half22float2(*(const __half2*)(qkv + a + 1024));
        float2 fv = __half22float2(*(const __half2*)(qkv + a + 2048));
        q[n][d2] = fq.x; q[n][d2 + 1] = fq.y;
        k[n][d2] = fk.x; k[n][d2 + 1] = fk.y;
        v[n][d2] = fv.x; v[n][d2 + 1] = fv.y;
    }
    __syncthreads();

    {
        const int n  = tid >> 2;
        const int mb = tid & 3;
        const float* rbp = rel_bias + ((size_t)h * 32 + n) * 32;
#pragma unroll
        for (int j = 0; j < 8; ++j) {
            int m = mb + 4 * j;
            float acc = 0.f;
#pragma unroll
            for (int d = 0; d < 64; ++d) acc += q[n][d] * k[m][d];
            s[n][m] = acc * 0.125f + rbp[m];
        }
    }
    __syncthreads();

    {
        const int lane = tid & 31, w = tid >> 5;
        for (int rr = w * 8; rr < w * 8 + 8; ++rr) {
            float x = s[rr][lane];
            float mx = x;
#pragma unroll
            for (int off = 16; off > 0; off >>= 1)
                mx = fmaxf(mx, __shfl_xor_sync(0xFFFFFFFFu, mx, off));
            float e = __expf(x - mx);
            float sum = e;
#pragma unroll
            for (int off = 16; off > 0; off >>= 1)
                sum += __shfl_xor_sync(0xFFFFFFFFu, sum, off);
            s[rr][lane] = e / sum;
        }
    }
    __syncthreads();

    // out = p @ v -> fp16 tiled (row = b*32+n, col = h*64+d), pairs of d
    for (int i = tid; i < SEQ * HEAD_D / 2; i += 128) {
        int n = i >> 5, d2 = (i & 31) << 1;
        float acc0 = 0.f, acc1 = 0.f;
#pragma unroll
        for (int m = 0; m < 32; ++m) {
            float p = s[n][m];
            acc0 += p * v[m][d2];
            acc1 += p * v[m][d2 + 1];
        }
        int row = b * SEQ + n;
        int col = h * HEAD_D + d2;
        *(__half2*)(attn_ts + tiled16_byte(row, col)) = __floats2half2_rn(acc0, acc1);
    }
}

// ============================================================================
// Launcher
// ============================================================================
extern "C" void kernel_launch(void* const* d_in, const int* in_sizes, int n_in,
                              void* d_out, int out_size)
{
    const float* x      = (const float*)d_in[0];
    const float* W_qkv  = (const float*)d_in[1];
    const float* b_qkv  = (const float*)d_in[2];
    const float* W_proj = (const float*)d_in[3];
    const float* b_proj = (const float*)d_in[4];
    const float* rbias  = (const float*)d_in[5];

    void *p_qkv = nullptr, *p_xs = nullptr, *p_at = nullptr,
         *p_wq = nullptr, *p_wp = nullptr;
    cudaGetSymbolAddress(&p_qkv, g_qkv16);
    cudaGetSymbolAddress(&p_xs,  g_xs16);
    cudaGetSymbolAddress(&p_at,  g_at16);
    cudaGetSymbolAddress(&p_wq,  g_wq16);
    cudaGetSymbolAddress(&p_wp,  g_wp16);

    cudaFuncSetAttribute(gemm_f16_kernel<true>,
                         cudaFuncAttributeMaxDynamicSharedMemorySize, GEMM_SMEM);
    cudaFuncSetAttribute(gemm_f16_kernel<false>,
                         cudaFuncAttributeMaxDynamicSharedMemorySize, GEMM_SMEM);

    // Pre-pass: convert + tile (x, W_qkv, W_proj) to fp16
    convert_tile16_kernel<<<((size_t)MDIM * KDIM / 4 + 255) / 256, 256>>>(
        x, (unsigned char*)p_xs, MDIM, KDIM);
    convert_tile16_kernel<<<((size_t)NQKV * KDIM / 4 + 255) / 256, 256>>>(
        W_qkv, (unsigned char*)p_wq, NQKV, KDIM);
    convert_tile16_kernel<<<((size_t)NPROJ * KDIM / 4 + 255) / 256, 256>>>(
        W_proj, (unsigned char*)p_wp, NPROJ, KDIM);

    // GEMM1: qkv = x @ W_qkv^T + b_qkv  [65536 x 3072] -> fp16 out
    gemm_f16_kernel<true><<<(MDIM / 128) * (NQKV / 128), 256, GEMM_SMEM>>>(
        (const unsigned char*)p_xs, (const unsigned char*)p_wq, b_qkv,
        p_qkv, MDIM, NQKV);

    // Attention: 2048*16 (b,h) blocks -> fp16 tiled scratch
    attn_kernel<<<BATCH * HEADS, 128>>>(
        (const __half*)p_qkv, rbias, (unsigned char*)p_at);

    // GEMM2: out = attn @ W_proj^T + b_proj  [65536 x 1024] -> fp32 out
    gemm_f16_kernel<false><<<(MDIM / 128) * (NPROJ / 128), 256, GEMM_SMEM>>>(
        (const unsigned char*)p_at, (const unsigned char*)p_wp, b_proj,
        d_out, MDIM, NPROJ);
}